// round 16
// baseline (speedup 1.0000x reference)
#include <cuda_runtime.h>

#define GN 512
#define GBATCH 16
#define RSTRIP 8
#define NSTRIPS 64                // GN / RSTRIP
#define NTILES 5                  // windows at 0,96,192,288,384 (all in-grid)
#define MAXITER 20
#define KFUSE 4
#define WARMUP 9                  // level skew 2 -> first store at t=9
#define NSTEPS (RSTRIP + WARMUP)  // 17
#define NPTS (GBATCH * GN * GN)

// Scratch ping-pong buffer + pre-scaled b (16 MB each) — __device__ globals.
__device__ float g_scratch[NPTS];
__device__ float g_bq[NPTS];

__device__ __forceinline__ float4 ld4(const float* p) {
    return *reinterpret_cast<const float4*>(p);
}
template<bool G>
__device__ __forceinline__ float4 ldx(const float* p, int row, int cbase) {
    if (G) return ((unsigned)row < GN) ? ld4(p + row * GN + cbase)
                                       : make_float4(0.f, 0.f, 0.f, 0.f);
    return ld4(p + row * GN + cbase);
}

// Prologue: bq = 0.25 * b (pre-scaled once; removes 16 FMUL/step from the
// jacobi mainloop across all 5 fused launches).
__global__ void __launch_bounds__(256) prescale_b(const float* __restrict__ b) {
    int i = (blockIdx.x * 256 + threadIdx.x) * 4;
    float4 v = ld4(b + i);
    v.x *= 0.25f; v.y *= 0.25f; v.z *= 0.25f; v.w *= 0.25f;
    *reinterpret_cast<float4*>(g_bq + i) = v;
}

// Jacobi row update; b4 is PRE-SCALED by 0.25. Lane 0's left / lane 31's
// right neighbor forced to 0: exact Dirichlet at grid-edge windows, harmless
// inside the >=4-col discard margin at internal window seams.
__device__ __forceinline__ float4 jrowf(float4 up, float4 mid, float4 dn,
                                        float4 b4, int lane)
{
    float l = __shfl_up_sync(0xffffffffu, mid.w, 1);
    float r = __shfl_down_sync(0xffffffffu, mid.x, 1);
    if (lane == 0)  l = 0.f;
    if (lane == 31) r = 0.f;
    float4 res;
    res.x = fmaf((l     + mid.y) + (up.x + dn.x), 0.25f, b4.x);
    res.y = fmaf((mid.x + mid.z) + (up.y + dn.y), 0.25f, b4.y);
    res.z = fmaf((mid.y + mid.w) + (up.z + dn.z), 0.25f, b4.z);
    res.w = fmaf((mid.z + r    ) + (up.w + dn.w), 0.25f, b4.w);
    return res;
}

// Level-skewed (skew 2) 4-deep Jacobi pipeline, depth-1 load prefetch.
// At step t (a = r0-3+t): prefetch x[a+2], bq[a+1] for step t+1;
// L1 -> row a; L2 -> row a-2; L3 -> row a-4; L4 (store) -> row a-6 from
// t >= WARMUP. Lagged bq rows (a-2, a-4, a-6) re-loaded from L1 (already
// scaled). All four level updates per step are mutually independent;
// Z-initialized rings feed only discarded rows.
// G=true adds two-sided row guards on loads and every level.
template<bool G>
__device__ __forceinline__ void march(const float* __restrict__ xg,
                                      const float* __restrict__ bg,
                                      float* __restrict__ og,
                                      int r0, int cbase, bool vs, int lane)
{
    const float4 Z = make_float4(0.f, 0.f, 0.f, 0.f);

    float4 xm = ldx<G>(xg, r0 - 4, cbase);   // x row a-1 @ t=0
    float4 xc = ldx<G>(xg, r0 - 3, cbase);   // x row a   @ t=0
    float4 xp = ldx<G>(xg, r0 - 2, cbase);   // x row a+1 @ t=0
    float4 bb = ldx<G>(bg, r0 - 3, cbase);   // bq row a  @ t=0

    float4 p1b = Z, p1c = Z, p1d = Z;        // L1 rows a-1, a-2, a-3
    float4 p2b = Z, p2c = Z, p2d = Z;        // L2 rows a-3, a-4, a-5
    float4 p3b = Z, p3c = Z, p3d = Z;        // L3 rows a-5, a-6, a-7

    #pragma unroll
    for (int t = 0; t < NSTEPS; ++t) {
        const int a = r0 - 3 + t;

        // prefetch for step t+1
        float4 xn = ldx<G>(xg, a + 2, cbase);
        float4 bn = ldx<G>(bg, a + 1, cbase);

        // lagged bq rows from L1 (fetched by this warp steps ago, pre-scaled)
        float4 b2 = ldx<G>(bg, a - 2, cbase);
        float4 b4 = ldx<G>(bg, a - 4, cbase);

        // four INDEPENDENT level updates (inputs all from steps <= t-1)
        float4 pn1 = (!G || (unsigned)a < GN)
                   ? jrowf(xm, xc, xp, bb, lane) : Z;          // L1 row a
        float4 pn2 = (!G || (unsigned)(a - 2) < GN)
                   ? jrowf(p1d, p1c, p1b, b2, lane) : Z;       // L2 row a-2
        float4 pn3 = (!G || (unsigned)(a - 4) < GN)
                   ? jrowf(p2d, p2c, p2b, b4, lane) : Z;       // L3 row a-4

        if (t >= WARMUP) {                                     // L4 row a-6
            float4 b6 = ldx<G>(bg, a - 6, cbase);
            float4 res = jrowf(p3d, p3c, p3b, b6, lane);
            if (vs) *reinterpret_cast<float4*>(og + (a - 6) * GN + cbase) = res;
        }

        // lockstep ring shifts (renamed by ptxas, no real MOVs)
        xm = xc; xc = xp; xp = xn; bb = bn;
        p1d = p1c; p1c = p1b; p1b = pn1;
        p2d = p2c; p2c = p2b; p2b = pn2;
        p3d = p3c; p3c = p3b; p3b = pn3;
    }
}

// src_sel: 0 = u, 1 = g_scratch, 2 = out ; dst_sel: 0 = out, 1 = g_scratch
__global__ void __launch_bounds__(128, 6) jacobi4(
    const float* __restrict__ u,
    float* __restrict__ out,
    int src_sel, int dst_sel)
{
    const float* x = (src_sel == 0) ? u
                   : (src_sel == 1) ? (const float*)g_scratch
                                    : (const float*)out;
    float* o = dst_sel ? g_scratch : out;

    const int lane  = threadIdx.x & 31;
    const int wid   = threadIdx.x >> 5;
    const int strip = blockIdx.x * 4 + wid;         // 0..63
    const int r0    = strip * RSTRIP;
    const int ty    = blockIdx.y;
    const int wb    = ty * 96;                      // window base: 0..384
    const int cbase = wb + lane * 4;                // ALWAYS in [0, 508]
    const int slo   = (ty == 0)          ? 0  : wb + 4;
    const int shi   = (ty == NTILES - 1) ? GN : wb + 100;
    const bool vs   = (cbase >= slo) && (cbase < shi);

    const size_t base = (size_t)blockIdx.z * (GN * GN);
    const float* xg = x + base;
    const float* bg = g_bq + base;
    float*       og = o + base;

    // rows touched: bq down to r0-7 (lagged b4 at t=0), x up to r0+15;
    // fast path needs r0 >= 8 and r0 + 15 <= 511 -> strips 1..62.
    if ((r0 >= RSTRIP) && (r0 + 15 < GN))
        march<false>(xg, bg, og, r0, cbase, vs, lane);
    else
        march<true >(xg, bg, og, r0, cbase, vs, lane);
}

extern "C" void kernel_launch(void* const* d_in, const int* in_sizes, int n_in,
                              void* d_out, int out_size)
{
    const float* u = (const float*)d_in[0];
    const float* b = (const float*)d_in[1];
    float* out = (float*)d_out;

    // prologue: bq = 0.25 * b (once per replay, reused by all 5 launches)
    prescale_b<<<NPTS / (256 * 4), 256>>>(b);

    dim3 block(128);                           // 4 independent warps (4 strips)
    dim3 grid(NSTRIPS / 4, NTILES, GBATCH);    // 16 x 5 x 16 = 1280 blocks

    const int nfused = MAXITER / KFUSE;        // 5 launches, 4 sweeps each
    int prev_dst = -1;
    for (int f = 0; f < nfused; ++f) {
        int dst = ((nfused - 1 - f) & 1);              // last one lands in out
        int src = (f == 0) ? 0 : (prev_dst ? 1 : 2);
        jacobi4<<<grid, block>>>(u, out, src, dst);
        prev_dst = dst;
    }
}

// round 17
// speedup vs baseline: 1.2336x; 1.2336x over previous
#include <cuda_runtime.h>

#define GN 512
#define GBATCH 16
#define RSTRIP 8
#define NSTRIPS 64                // GN / RSTRIP
#define NTILES 5                  // windows at 0,96,192,288,384 (all in-grid)
#define MAXITER 20
#define KFUSE 4
#define WARMUP 9                  // level skew 2 -> first store at t=9
#define NSTEPS (RSTRIP + WARMUP)  // 17

// Scratch ping-pong buffer (16 MB) — __device__ global, no runtime allocation.
__device__ float g_scratch[GBATCH * GN * GN];

__device__ __forceinline__ float4 ld4(const float* p) {
    return *reinterpret_cast<const float4*>(p);
}
template<bool G>
__device__ __forceinline__ float4 ldx(const float* p, int row, int cbase) {
    if (G) return ((unsigned)row < GN) ? ld4(p + row * GN + cbase)
                                       : make_float4(0.f, 0.f, 0.f, 0.f);
    return ld4(p + row * GN + cbase);
}

// Scaled-iterate cascade: w_k = 4^k * x_k, so levels 1..3 are
//   w_k = N(w_{k-1}) + 4^{k-1} * b          (b RAW, coeff as FFMA immediate)
// and the store level is x_4 = N(w_3)/256 + b/4. All scale factors are
// powers of two -> bit-exact vs the plain recursion, and no FMULs on b loads.
// Lane 0 left / lane 31 right neighbor forced to 0: exact Dirichlet at
// grid-edge windows, harmless inside the >=4-col discard margin at seams.
template<int CK>
__device__ __forceinline__ float4 jrowk(float4 up, float4 mid, float4 dn,
                                        float4 bv, int lane)
{
    float l = __shfl_up_sync(0xffffffffu, mid.w, 1);
    float r = __shfl_down_sync(0xffffffffu, mid.x, 1);
    if (lane == 0)  l = 0.f;
    if (lane == 31) r = 0.f;
    const float ck = (float)CK;
    float4 res;
    res.x = fmaf(bv.x, ck, (l     + mid.y) + (up.x + dn.x));
    res.y = fmaf(bv.y, ck, (mid.x + mid.z) + (up.y + dn.y));
    res.z = fmaf(bv.z, ck, (mid.y + mid.w) + (up.z + dn.z));
    res.w = fmaf(bv.w, ck, (mid.z + r    ) + (up.w + dn.w));
    return res;
}

// Store level: x4 = N(w3) * (1/256) + 0.25 * b
__device__ __forceinline__ float4 jrow4(float4 up, float4 mid, float4 dn,
                                        float4 bv, int lane)
{
    float l = __shfl_up_sync(0xffffffffu, mid.w, 1);
    float r = __shfl_down_sync(0xffffffffu, mid.x, 1);
    if (lane == 0)  l = 0.f;
    if (lane == 31) r = 0.f;
    const float s = 1.f / 256.f;
    float4 res;
    res.x = fmaf((l     + mid.y) + (up.x + dn.x), s, 0.25f * bv.x);
    res.y = fmaf((mid.x + mid.z) + (up.y + dn.y), s, 0.25f * bv.y);
    res.z = fmaf((mid.y + mid.w) + (up.z + dn.z), s, 0.25f * bv.z);
    res.w = fmaf((mid.z + r    ) + (up.w + dn.w), s, 0.25f * bv.w);
    return res;
}

// Level-skewed (skew 2) 4-deep scaled-Jacobi pipeline, depth-1 prefetch.
// At step t (a = r0-3+t): prefetch x[a+2], b[a+1] for step t+1;
// L1 -> row a; L2 -> row a-2; L3 -> row a-4; L4 (store) -> row a-6 from
// t >= WARMUP. Lagged b rows (a-2, a-4, a-6) re-loaded RAW from L1.
// All four level updates per step are mutually independent (inputs from
// steps <= t-1); Z-initialized rings feed only discarded rows.
// G=true adds two-sided row guards on loads and every level.
template<bool G>
__device__ __forceinline__ void march(const float* __restrict__ xg,
                                      const float* __restrict__ bg,
                                      float* __restrict__ og,
                                      int r0, int cbase, bool vs, int lane)
{
    const float4 Z = make_float4(0.f, 0.f, 0.f, 0.f);

    float4 xm = ldx<G>(xg, r0 - 4, cbase);   // x row a-1 @ t=0
    float4 xc = ldx<G>(xg, r0 - 3, cbase);   // x row a   @ t=0
    float4 xp = ldx<G>(xg, r0 - 2, cbase);   // x row a+1 @ t=0
    float4 bb = ldx<G>(bg, r0 - 3, cbase);   // b row a   @ t=0

    float4 p1b = Z, p1c = Z, p1d = Z;        // w1 rows a-1, a-2, a-3
    float4 p2b = Z, p2c = Z, p2d = Z;        // w2 rows a-3, a-4, a-5
    float4 p3b = Z, p3c = Z, p3d = Z;        // w3 rows a-5, a-6, a-7

    #pragma unroll
    for (int t = 0; t < NSTEPS; ++t) {
        const int a = r0 - 3 + t;

        // prefetch for step t+1
        float4 xn = ldx<G>(xg, a + 2, cbase);
        float4 bn = ldx<G>(bg, a + 1, cbase);

        // lagged RAW b rows from L1 (fetched by this warp steps ago)
        float4 b2 = ldx<G>(bg, a - 2, cbase);
        float4 b4 = ldx<G>(bg, a - 4, cbase);

        // four INDEPENDENT level updates (inputs all from steps <= t-1)
        float4 pn1 = (!G || (unsigned)a < GN)
                   ? jrowk<1>(xm, xc, xp, bb, lane) : Z;        // w1 row a
        float4 pn2 = (!G || (unsigned)(a - 2) < GN)
                   ? jrowk<4>(p1d, p1c, p1b, b2, lane) : Z;     // w2 row a-2
        float4 pn3 = (!G || (unsigned)(a - 4) < GN)
                   ? jrowk<16>(p2d, p2c, p2b, b4, lane) : Z;    // w3 row a-4

        if (t >= WARMUP) {                                      // x4 row a-6
            float4 b6 = ldx<G>(bg, a - 6, cbase);
            float4 res = jrow4(p3d, p3c, p3b, b6, lane);
            if (vs) *reinterpret_cast<float4*>(og + (a - 6) * GN + cbase) = res;
        }

        // lockstep ring shifts (renamed by ptxas, no real MOVs)
        xm = xc; xc = xp; xp = xn; bb = bn;
        p1d = p1c; p1c = p1b; p1b = pn1;
        p2d = p2c; p2c = p2b; p2b = pn2;
        p3d = p3c; p3c = p3b; p3b = pn3;
    }
}

// src_sel: 0 = u, 1 = g_scratch, 2 = out ; dst_sel: 0 = out, 1 = g_scratch
__global__ void __launch_bounds__(128, 6) jacobi4(
    const float* __restrict__ u,
    const float* __restrict__ b,
    float* __restrict__ out,
    int src_sel, int dst_sel)
{
    const float* x = (src_sel == 0) ? u
                   : (src_sel == 1) ? (const float*)g_scratch
                                    : (const float*)out;
    float* o = dst_sel ? g_scratch : out;

    const int lane  = threadIdx.x & 31;
    const int wid   = threadIdx.x >> 5;
    const int strip = blockIdx.x * 4 + wid;         // 0..63
    const int r0    = strip * RSTRIP;
    const int ty    = blockIdx.y;
    const int wb    = ty * 96;                      // window base: 0..384
    const int cbase = wb + lane * 4;                // ALWAYS in [0, 508]
    const int slo   = (ty == 0)          ? 0  : wb + 4;
    const int shi   = (ty == NTILES - 1) ? GN : wb + 100;
    const bool vs   = (cbase >= slo) && (cbase < shi);

    const size_t base = (size_t)blockIdx.z * (GN * GN);
    const float* xg = x + base;
    const float* bg = b + base;
    float*       og = o + base;

    // rows touched: b down to r0-7 (lagged b4 at t=0), x up to r0+15;
    // fast path: strips 1..62; guarded: strips 0 and 63.
    if ((r0 >= RSTRIP) && (r0 + 15 < GN))
        march<false>(xg, bg, og, r0, cbase, vs, lane);
    else
        march<true >(xg, bg, og, r0, cbase, vs, lane);
}

extern "C" void kernel_launch(void* const* d_in, const int* in_sizes, int n_in,
                              void* d_out, int out_size)
{
    const float* u = (const float*)d_in[0];
    const float* b = (const float*)d_in[1];
    float* out = (float*)d_out;

    dim3 block(128);                           // 4 independent warps (4 strips)
    dim3 grid(NSTRIPS / 4, NTILES, GBATCH);    // 16 x 5 x 16 = 1280 blocks

    const int nfused = MAXITER / KFUSE;        // 5 launches, 4 sweeps each
    int prev_dst = -1;
    for (int f = 0; f < nfused; ++f) {
        int dst = ((nfused - 1 - f) & 1);              // last one lands in out
        int src = (f == 0) ? 0 : (prev_dst ? 1 : 2);
        jacobi4<<<grid, block>>>(u, b, out, src, dst);
        prev_dst = dst;
    }
}